// round 15
// baseline (speedup 1.0000x reference)
#include <cuda_runtime.h>
#include <cuda_fp16.h>
#include <cstdint>
#include <cstddef>

#define N_NODES 100000
#define N_EDGES 3200000
#define D_IN    512
#define D_HID   512
#define D_OUT   256

// ---------------- scratch (no cudaMalloc allowed) ----------------
__device__ __half g_h0h[(size_t)N_NODES * 512];   // fp16 SpMM gather src
__device__ __half g_h1h[(size_t)N_NODES * 512];   // fp16 SpMM out / GEMM1 A
__device__ __half g_h2h[(size_t)N_NODES * 512];   // fp16 mid GEMM out / GEMM2 A
__device__ int   g_rptr[N_NODES + 1];
__device__ int   g_cnt[N_NODES];
__device__ int   g_cur[N_NODES];
__device__ int2  g_edge[N_EDGES];                 // row-sorted {col, w bits}
#define SCAN_BLOCKS ((N_NODES + 1023) / 1024)     // 98
__device__ int   g_bsum[SCAN_BLOCKS];
// pre-converted fp16 weights: W0 @0, W1 @262144, W2 @524288
#define W_TOTAL 655360
__device__ __half g_Wh[W_TOTAL];

// ---------------- helpers ----------------
__device__ __forceinline__ float4 relu4(float4 a) {
    a.x = fmaxf(a.x, 0.f); a.y = fmaxf(a.y, 0.f);
    a.z = fmaxf(a.z, 0.f); a.w = fmaxf(a.w, 0.f);
    return a;
}
__device__ __forceinline__ uint32_t smem_u32(const void* p) {
    uint32_t a;
    asm("{ .reg .u64 t; cvta.to.shared.u64 t, %1; cvt.u32.u64 %0, t; }" : "=r"(a) : "l"(p));
    return a;
}
__device__ __forceinline__ void ldsm4(uint32_t* r, uint32_t addr) {
    asm volatile("ldmatrix.sync.aligned.m8n8.x4.shared.b16 {%0,%1,%2,%3}, [%4];"
                 : "=r"(r[0]), "=r"(r[1]), "=r"(r[2]), "=r"(r[3]) : "r"(addr));
}
__device__ __forceinline__ void mma16816h(float* d, const uint32_t* a,
                                          uint32_t b0, uint32_t b1) {
    asm volatile(
        "mma.sync.aligned.m16n8k16.row.col.f32.f16.f16.f32 "
        "{%0,%1,%2,%3}, {%4,%5,%6,%7}, {%8,%9}, {%0,%1,%2,%3};"
        : "+f"(d[0]), "+f"(d[1]), "+f"(d[2]), "+f"(d[3])
        : "r"(a[0]), "r"(a[1]), "r"(a[2]), "r"(a[3]), "r"(b0), "r"(b1));
}
// accumulate one gathered fp16x8 slice: acc += w * v
__device__ __forceinline__ void acc8(float* acc, float w, uint4 v) {
    float2 f0 = __half22float2(*reinterpret_cast<__half2*>(&v.x));
    float2 f1 = __half22float2(*reinterpret_cast<__half2*>(&v.y));
    float2 f2 = __half22float2(*reinterpret_cast<__half2*>(&v.z));
    float2 f3 = __half22float2(*reinterpret_cast<__half2*>(&v.w));
    acc[0] = fmaf(w, f0.x, acc[0]); acc[1] = fmaf(w, f0.y, acc[1]);
    acc[2] = fmaf(w, f1.x, acc[2]); acc[3] = fmaf(w, f1.y, acc[3]);
    acc[4] = fmaf(w, f2.x, acc[4]); acc[5] = fmaf(w, f2.y, acc[5]);
    acc[6] = fmaf(w, f3.x, acc[6]); acc[7] = fmaf(w, f3.y, acc[7]);
}
__device__ __forceinline__ uint4 pack8(const float* a) {
    float4 o0 = relu4(make_float4(a[0], a[1], a[2], a[3]));
    float4 o1 = relu4(make_float4(a[4], a[5], a[6], a[7]));
    __half2 p0 = __floats2half2_rn(o0.x, o0.y);
    __half2 p1 = __floats2half2_rn(o0.z, o0.w);
    __half2 p2 = __floats2half2_rn(o1.x, o1.y);
    __half2 p3 = __floats2half2_rn(o1.z, o1.w);
    return make_uint4(*reinterpret_cast<uint32_t*>(&p0),
                      *reinterpret_cast<uint32_t*>(&p1),
                      *reinterpret_cast<uint32_t*>(&p2),
                      *reinterpret_cast<uint32_t*>(&p3));
}

// ---------------- weight conversion (tiny) ----------------
__global__ void convert_w_kernel(const float* __restrict__ W0,
                                 const float* __restrict__ W1,
                                 const float* __restrict__ W2) {
    int i = blockIdx.x * blockDim.x + threadIdx.x;
    if (i >= W_TOTAL) return;
    float v = (i < 262144) ? W0[i] : (i < 524288) ? W1[i - 262144] : W2[i - 524288];
    g_Wh[i] = __float2half_rn(v);
}

// ---------------- CSR build ----------------
__global__ void zero_counts_kernel() {
    int i = blockIdx.x * blockDim.x + threadIdx.x;
    if (i < N_NODES) { g_cnt[i] = 0; g_cur[i] = 0; }
}
__global__ void hist_kernel(const int* __restrict__ erow) {
    int e = blockIdx.x * blockDim.x + threadIdx.x;
    if (e < N_EDGES) atomicAdd(&g_cnt[erow[e]], 1);
}
__global__ void scan1_kernel() {
    __shared__ int s[1024];
    const int b = blockIdx.x, t = threadIdx.x;
    const int i = b * 1024 + t;
    int v = (i < N_NODES) ? g_cnt[i] : 0;
    s[t] = v;
    __syncthreads();
    #pragma unroll
    for (int off = 1; off < 1024; off <<= 1) {
        int x = (t >= off) ? s[t - off] : 0;
        __syncthreads();
        s[t] += x;
        __syncthreads();
    }
    if (i < N_NODES) g_rptr[i + 1] = s[t];
    if (t == 1023) g_bsum[b] = s[1023];
}
__global__ void scan2_kernel() {
    __shared__ int s[128];
    const int t = threadIdx.x;
    int v = (t < SCAN_BLOCKS) ? g_bsum[t] : 0;
    s[t] = v;
    __syncthreads();
    #pragma unroll
    for (int off = 1; off < 128; off <<= 1) {
        int x = (t >= off) ? s[t - off] : 0;
        __syncthreads();
        s[t] += x;
        __syncthreads();
    }
    if (t < SCAN_BLOCKS) g_bsum[t] = s[t] - v;   // exclusive
}
__global__ void scan3_kernel() {
    const int b = blockIdx.x, t = threadIdx.x;
    const int i = b * 1024 + t;
    if (i < N_NODES) g_rptr[i + 1] += g_bsum[b];
    if (i == 0) g_rptr[0] = 0;
}
__global__ void scatter_kernel(const int* __restrict__ erow,
                               const int* __restrict__ ecol,
                               const float* __restrict__ eval) {
    int e = blockIdx.x * blockDim.x + threadIdx.x;
    if (e < N_EDGES) {
        int r = erow[e];
        int pos = g_rptr[r] + atomicAdd(&g_cur[r], 1);
        g_edge[pos] = make_int2(ecol[e], __float_as_int(eval[e]));
    }
}

// ---------------- SpMM (+ReLU): fp16 gather, single pass over all 512 -----
// h0 (102.4 MB fp16) fits in L2; lane gathers 32B/edge (2x LDG.128).
__global__ void __launch_bounds__(256) spmm_relu_kernel()
{
    int gw   = (blockIdx.x * blockDim.x + threadIdx.x) >> 5;
    int lane = threadIdx.x & 31;
    if (gw >= N_NODES) return;
    int beg = g_rptr[gw], end = g_rptr[gw + 1];
    const __half* hbase = g_h0h + lane * 16;

    float acc[16];
    #pragma unroll
    for (int q = 0; q < 16; q++) acc[q] = 0.f;

    for (int b = beg; b < end; b += 32) {
        int n = end - b;
        if (n > 32) n = 32;
        int   c = 0;
        float w = 0.f;
        if (lane < n) {
            int2 ed = __ldcs(g_edge + b + lane);
            c = ed.x;
            w = __int_as_float(ed.y);
        }
        for (int j = 0; j < n; j++) {
            int   cj = __shfl_sync(0xffffffffu, c, j);
            float wj = __shfl_sync(0xffffffffu, w, j);
            const uint4* p = reinterpret_cast<const uint4*>(hbase + (size_t)cj * 512);
            uint4 va = p[0];
            uint4 vb = p[1];
            acc8(acc,     wj, va);
            acc8(acc + 8, wj, vb);
        }
    }
    __half* o = g_h1h + (size_t)gw * 512 + lane * 16;
    __stcs(reinterpret_cast<uint4*>(o),     pack8(acc));
    __stcs(reinterpret_cast<uint4*>(o) + 1, pack8(acc + 8));
}

// ---------------- mma.sync fp16 GEMM ----------------
// C[M,N] = A[M,512] * W[N,512]^T.  A fp32 (inline cvt) or fp16; W fp16.
// CTA tile 128x128, 16 warps (4m x 4n), warp tile 32x32.
// K chunks of 64, double-buffered SMEM.
#define MG_STAGE  32768
#define MG_A      0
#define MG_B      16384
#define MG_TOTAL  (2 * MG_STAGE)

template <bool A_HALF, bool RELU, bool HALF_OUT>
__global__ void __launch_bounds__(512) gemm_mma_kernel(
    const float* __restrict__ Af,
    const __half* __restrict__ Ah,
    const __half* __restrict__ B,
    float* __restrict__ C,
    __half* __restrict__ Ch,
    int M, int N)
{
    extern __shared__ char smem[];
    const int tid  = threadIdx.x;
    const int wid  = tid >> 5;
    const int lane = tid & 31;
    const int bm = blockIdx.y * 128;
    const int bn = blockIdx.x * 128;
    const int wm = wid >> 2;       // 0..3
    const int wn = wid & 3;        // 0..3
    const uint32_t sb = smem_u32(smem);

    float d[2][4][4];
    #pragma unroll
    for (int mi = 0; mi < 2; mi++)
        #pragma unroll
        for (int ni = 0; ni < 4; ni++)
            #pragma unroll
            for (int q = 0; q < 4; q++) d[mi][ni][q] = 0.f;

    float4 paf[4];
    uint4  pah[2], pb[2];

    const int lmat   = lane >> 3;
    const int a_rit  = ((lmat & 1) << 3) + (lane & 7);
    const int a_cadd = lmat >> 1;
    const int b_rit  = ((lmat >> 1) << 3) + (lane & 7);
    const int b_cadd = lmat & 1;

    int arow[2], brow[2];
    #pragma unroll
    for (int mi = 0; mi < 2; mi++) arow[mi] = wm * 32 + mi * 16 + a_rit;
    #pragma unroll
    for (int np = 0; np < 2; np++) brow[np] = wn * 32 + np * 16 + b_rit;

    #define LDG_CHUNK(kc) do {                                                     \
        const int k0_ = (kc) * 64;                                                 \
        if (A_HALF) {                                                              \
            _Pragma("unroll")                                                      \
            for (int i = 0; i < 2; i++) {                                          \
                int idx = tid + i * 512;                                           \
                int r = idx >> 3, c = idx & 7;                                     \
                int gr = bm + r;                                                   \
                pah[i] = (gr < M)                                                  \
                    ? __ldg(reinterpret_cast<const uint4*>(Ah + (size_t)gr * 512 + k0_) + c) \
                    : make_uint4(0u, 0u, 0u, 0u);                                  \
            }                                                                      \
        } else {                                                                   \
            _Pragma("unroll")                                                      \
            for (int i = 0; i < 4; i++) {                                          \
                int idx = tid + i * 512;                                           \
                int r = idx >> 4, c4 = idx & 15;                                   \
                int gr = bm + r;                                                   \
                paf[i] = (gr < M)                                                  \
                    ? __ldg(reinterpret_cast<const float4*>(Af + (size_t)gr * 512 + k0_ + c4 * 4)) \
                    : make_float4(0.f, 0.f, 0.f, 0.f);                             \
            }                                                                      \
        }                                                                          \
        _Pragma("unroll")                                                          \
        for (int i = 0; i < 2; i++) {                                              \
            int idx = tid + i * 512;                                               \
            int r = idx >> 3, c = idx & 7;                                         \
            size_t go = (size_t)(bn + r) * 512 + k0_;                              \
            pb[i] = __ldg(reinterpret_cast<const uint4*>(B + go) + c);             \
        }                                                                          \
    } while (0)

    #define STS_CHUNK(s) do {                                                      \
        char* st_ = smem + (s) * MG_STAGE;                                         \
        if (A_HALF) {                                                              \
            _Pragma("unroll")                                                      \
            for (int i = 0; i < 2; i++) {                                          \
                int idx = tid + i * 512;                                           \
                int r = idx >> 3, c = idx & 7;                                     \
                uint32_t off = (uint32_t)(r * 128 + ((c ^ (r & 7)) << 4));         \
                *reinterpret_cast<uint4*>(st_ + MG_A + off) = pah[i];              \
            }                                                                      \
        } else {                                                                   \
            _Pragma("unroll")                                                      \
            for (int i = 0; i < 4; i++) {                                          \
                int idx = tid + i * 512;                                           \
                int r = idx >> 4, c4 = idx & 15;                                   \
                float4 v = paf[i];                                                 \
                __half2 h01 = __floats2half2_rn(v.x, v.y);                         \
                __half2 h23 = __floats2half2_rn(v.z, v.w);                         \
                int c = c4 >> 1, half = (c4 & 1) * 8;                              \
                uint32_t off = (uint32_t)(r * 128 + ((c ^ (r & 7)) << 4) + half);  \
                *reinterpret_cast<uint2*>(st_ + MG_A + off) =                      \
                    make_uint2(*reinterpret_cast<uint32_t*>(&h01),                 \
                               *reinterpret_cast<uint32_t*>(&h23));                \
            }                                                                      \
        }                                                                          \
        _Pragma("unroll")                                                          \
        for (int i = 0; i < 2; i++) {                                              \
            int idx = tid + i * 512;                                               \
            int r = idx >> 3, c = idx & 7;                                         \
            uint32_t off = (uint32_t)(r * 128 + ((c ^ (r & 7)) << 4));             \
            *reinterpret_cast<uint4*>(st_ + MG_B + off) = pb[i];                   \
        }                                                                          \
    } while (0)

    LDG_CHUNK(0);
    STS_CHUNK(0);
    __syncthreads();

    for (int kc = 0; kc < 8; kc++) {
        if (kc < 7) LDG_CHUNK(kc + 1);

        {
            const uint32_t ba = sb + (kc & 1) * MG_STAGE + MG_A;
            const uint32_t bb = sb + (kc & 1) * MG_STAGE + MG_B;
            #pragma unroll
            for (int ks = 0; ks < 4; ks++) {
                uint32_t af[2][4], bf[2][4];
                #pragma unroll
                for (int mi = 0; mi < 2; mi++) {
                    int cA = ks * 2 + a_cadd;
                    uint32_t off = (uint32_t)(arow[mi] * 128 + ((cA ^ (arow[mi] & 7)) << 4));
                    ldsm4(af[mi], ba + off);
                }
                #pragma unroll
                for (int np = 0; np < 2; np++) {
                    int cB = ks * 2 + b_cadd;
                    uint32_t off = (uint32_t)(brow[np] * 128 + ((cB ^ (brow[np] & 7)) << 4));
                    ldsm4(bf[np], bb + off);
                }
                #pragma unroll
                for (int mi = 0; mi < 2; mi++)
                    #pragma unroll
                    for (int np = 0; np < 2; np++)
                        #pragma unroll
                        for (int sub = 0; sub < 2; sub++)
                            mma16816h(d[mi][np * 2 + sub], af[mi],
                                      bf[np][sub * 2], bf[np][sub * 2 + 1]);
            }
        }

        if (kc < 7) STS_CHUNK((kc + 1) & 1);
        __syncthreads();
    }

    const int grp = lane >> 2;
    const int tg  = lane & 3;
    #pragma unroll
    for (int mi = 0; mi < 2; mi++) {
        #pragma unroll
        for (int ni = 0; ni < 4; ni++) {
            int row = bm + wm * 32 + mi * 16 + grp;
            int col = bn + wn * 32 + ni * 8 + tg * 2;
            float2 v0 = make_float2(d[mi][ni][0], d[mi][ni][1]);
            float2 v1 = make_float2(d[mi][ni][2], d[mi][ni][3]);
            if (RELU) {
                v0.x = fmaxf(v0.x, 0.f); v0.y = fmaxf(v0.y, 0.f);
                v1.x = fmaxf(v1.x, 0.f); v1.y = fmaxf(v1.y, 0.f);
            }
            if (HALF_OUT) {
                if (row < M)
                    *reinterpret_cast<__half2*>(Ch + (size_t)row * N + col) =
                        __floats2half2_rn(v0.x, v0.y);
                if (row + 8 < M)
                    *reinterpret_cast<__half2*>(Ch + (size_t)(row + 8) * N + col) =
                        __floats2half2_rn(v1.x, v1.y);
            } else {
                if (row < M)
                    *reinterpret_cast<float2*>(C + (size_t)row * N + col) = v0;
                if (row + 8 < M)
                    *reinterpret_cast<float2*>(C + (size_t)(row + 8) * N + col) = v1;
            }
        }
    }
    #undef LDG_CHUNK
    #undef STS_CHUNK
}

// ---------------- launch ----------------
extern "C" void kernel_launch(void* const* d_in, const int* in_sizes, int n_in,
                              void* d_out, int out_size)
{
    const float* x    = (const float*)d_in[0];
    const int*   erow = (const int*)  d_in[1];
    const int*   ecol = (const int*)  d_in[2];
    const float* eval = (const float*)d_in[3];
    const float* W0   = (const float*)d_in[4];
    const float* W1   = (const float*)d_in[5];
    const float* W2   = (const float*)d_in[6];
    float* out = (float*)d_out;

    __half *h0h, *h1h, *h2h, *wh;
    cudaGetSymbolAddress((void**)&h0h, g_h0h);
    cudaGetSymbolAddress((void**)&h1h, g_h1h);
    cudaGetSymbolAddress((void**)&h2h, g_h2h);
    cudaGetSymbolAddress((void**)&wh,  g_Wh);

    cudaFuncSetAttribute(gemm_mma_kernel<false, false, true>,
                         cudaFuncAttributeMaxDynamicSharedMemorySize, MG_TOTAL);
    cudaFuncSetAttribute(gemm_mma_kernel<true, true, true>,
                         cudaFuncAttributeMaxDynamicSharedMemorySize, MG_TOTAL);
    cudaFuncSetAttribute(gemm_mma_kernel<true, false, false>,
                         cudaFuncAttributeMaxDynamicSharedMemorySize, MG_TOTAL);

    static cudaStream_t s_side = nullptr;
    static cudaEvent_t  s_fork = nullptr, s_join = nullptr;
    if (s_side == nullptr) {
        cudaStreamCreateWithFlags(&s_side, cudaStreamNonBlocking);
        cudaEventCreateWithFlags(&s_fork, cudaEventDisableTiming);
        cudaEventCreateWithFlags(&s_join, cudaEventDisableTiming);
    }

    // fork: CSR build on side stream, concurrent with convert_w + GEMM0
    cudaEventRecord(s_fork, 0);
    cudaStreamWaitEvent(s_side, s_fork, 0);
    zero_counts_kernel<<<(N_NODES + 255) / 256, 256, 0, s_side>>>();
    hist_kernel<<<(N_EDGES + 255) / 256, 256, 0, s_side>>>(erow);
    scan1_kernel<<<SCAN_BLOCKS, 1024, 0, s_side>>>();
    scan2_kernel<<<1, 128, 0, s_side>>>();
    scan3_kernel<<<SCAN_BLOCKS, 1024, 0, s_side>>>();
    scatter_kernel<<<(N_EDGES + 255) / 256, 256, 0, s_side>>>(erow, ecol, eval);
    cudaEventRecord(s_join, s_side);

    // main stream: weight conversion + GEMM0
    convert_w_kernel<<<(W_TOTAL + 255) / 256, 256>>>(W0, W1, W2);
    const int mtiles = (N_NODES + 127) / 128;
    gemm_mma_kernel<false, false, true><<<dim3(4, mtiles), 512, MG_TOTAL>>>(
        x, nullptr, wh, nullptr, h0h, N_NODES, D_HID);

    // join: SpMM needs both GEMM0 (main) and CSR (side)
    cudaStreamWaitEvent(0, s_join, 0);
    spmm_relu_kernel<<<(N_NODES * 32 + 255) / 256, 256>>>();
    // h2 = relu(h1 @ W1^T)  (fp16 A, fp16 out)
    gemm_mma_kernel<true, true, true><<<dim3(4, mtiles), 512, MG_TOTAL>>>(
        nullptr, h1h, wh + 262144, nullptr, h2h, N_NODES, D_HID);
    // out = h2 @ W2^T  (fp16 A, fp32 out)
    gemm_mma_kernel<true, false, false><<<dim3(2, mtiles), 512, MG_TOTAL>>>(
        nullptr, h2h, wh + 524288, out, nullptr, N_NODES, D_OUT);
}

// round 16
// speedup vs baseline: 1.0805x; 1.0805x over previous
#include <cuda_runtime.h>
#include <cuda_fp16.h>
#include <cstdint>
#include <cstddef>

#define N_NODES 100000
#define N_EDGES 3200000
#define D_IN    512
#define D_HID   512
#define D_OUT   256

// ---------------- scratch (no cudaMalloc allowed) ----------------
__device__ __half g_h0h[(size_t)N_NODES * 512];   // fp16 SpMM gather src
__device__ __half g_h1h[(size_t)N_NODES * 512];   // fp16 SpMM out / GEMM1 A
__device__ __half g_h2h[(size_t)N_NODES * 512];   // fp16 mid GEMM out / GEMM2 A
__device__ int   g_rptr[N_NODES + 1];
__device__ int   g_cnt[N_NODES];
__device__ int   g_cur[N_NODES];
__device__ int2  g_edge[N_EDGES];                 // row-sorted {col, w bits}
#define SCAN_BLOCKS ((N_NODES + 1023) / 1024)     // 98
__device__ int   g_bsum[SCAN_BLOCKS];
// fp16 weights: W1 @262144, W2 @524288 (W0 consumed fp32 by GEMM0 directly)
#define W_TOTAL 655360
#define W12_TOTAL 393216
__device__ __half g_Wh[W_TOTAL];

// ---------------- helpers ----------------
__device__ __forceinline__ float4 relu4(float4 a) {
    a.x = fmaxf(a.x, 0.f); a.y = fmaxf(a.y, 0.f);
    a.z = fmaxf(a.z, 0.f); a.w = fmaxf(a.w, 0.f);
    return a;
}
__device__ __forceinline__ uint32_t smem_u32(const void* p) {
    uint32_t a;
    asm("{ .reg .u64 t; cvta.to.shared.u64 t, %1; cvt.u32.u64 %0, t; }" : "=r"(a) : "l"(p));
    return a;
}
__device__ __forceinline__ void ldsm4(uint32_t* r, uint32_t addr) {
    asm volatile("ldmatrix.sync.aligned.m8n8.x4.shared.b16 {%0,%1,%2,%3}, [%4];"
                 : "=r"(r[0]), "=r"(r[1]), "=r"(r[2]), "=r"(r[3]) : "r"(addr));
}
__device__ __forceinline__ void mma16816h(float* d, const uint32_t* a,
                                          uint32_t b0, uint32_t b1) {
    asm volatile(
        "mma.sync.aligned.m16n8k16.row.col.f32.f16.f16.f32 "
        "{%0,%1,%2,%3}, {%4,%5,%6,%7}, {%8,%9}, {%0,%1,%2,%3};"
        : "+f"(d[0]), "+f"(d[1]), "+f"(d[2]), "+f"(d[3])
        : "r"(a[0]), "r"(a[1]), "r"(a[2]), "r"(a[3]), "r"(b0), "r"(b1));
}
// accumulate one gathered fp16x8 slice: acc += w * v
__device__ __forceinline__ void acc8(float* acc, float w, uint4 v) {
    float2 f0 = __half22float2(*reinterpret_cast<__half2*>(&v.x));
    float2 f1 = __half22float2(*reinterpret_cast<__half2*>(&v.y));
    float2 f2 = __half22float2(*reinterpret_cast<__half2*>(&v.z));
    float2 f3 = __half22float2(*reinterpret_cast<__half2*>(&v.w));
    acc[0] = fmaf(w, f0.x, acc[0]); acc[1] = fmaf(w, f0.y, acc[1]);
    acc[2] = fmaf(w, f1.x, acc[2]); acc[3] = fmaf(w, f1.y, acc[3]);
    acc[4] = fmaf(w, f2.x, acc[4]); acc[5] = fmaf(w, f2.y, acc[5]);
    acc[6] = fmaf(w, f3.x, acc[6]); acc[7] = fmaf(w, f3.y, acc[7]);
}
__device__ __forceinline__ uint4 pack8(const float* a) {
    float4 o0 = relu4(make_float4(a[0], a[1], a[2], a[3]));
    float4 o1 = relu4(make_float4(a[4], a[5], a[6], a[7]));
    __half2 p0 = __floats2half2_rn(o0.x, o0.y);
    __half2 p1 = __floats2half2_rn(o0.z, o0.w);
    __half2 p2 = __floats2half2_rn(o1.x, o1.y);
    __half2 p3 = __floats2half2_rn(o1.z, o1.w);
    return make_uint4(*reinterpret_cast<uint32_t*>(&p0),
                      *reinterpret_cast<uint32_t*>(&p1),
                      *reinterpret_cast<uint32_t*>(&p2),
                      *reinterpret_cast<uint32_t*>(&p3));
}

// ---------------- weight conversion (W1, W2 only; on side stream) ---------
__global__ void convert_w_kernel(const float* __restrict__ W1,
                                 const float* __restrict__ W2) {
    int i = blockIdx.x * blockDim.x + threadIdx.x;
    if (i >= W12_TOTAL) return;
    float v = (i < 262144) ? W1[i] : W2[i - 262144];
    g_Wh[262144 + i] = __float2half_rn(v);
}

// ---------------- CSR build ----------------
__global__ void zero_counts_kernel() {
    int i = blockIdx.x * blockDim.x + threadIdx.x;
    if (i < N_NODES) { g_cnt[i] = 0; g_cur[i] = 0; }
}
__global__ void hist_kernel(const int* __restrict__ erow) {
    int e = blockIdx.x * blockDim.x + threadIdx.x;
    if (e < N_EDGES) atomicAdd(&g_cnt[erow[e]], 1);
}
__global__ void scan1_kernel() {
    __shared__ int s[1024];
    const int b = blockIdx.x, t = threadIdx.x;
    const int i = b * 1024 + t;
    int v = (i < N_NODES) ? g_cnt[i] : 0;
    s[t] = v;
    __syncthreads();
    #pragma unroll
    for (int off = 1; off < 1024; off <<= 1) {
        int x = (t >= off) ? s[t - off] : 0;
        __syncthreads();
        s[t] += x;
        __syncthreads();
    }
    if (i < N_NODES) g_rptr[i + 1] = s[t];
    if (t == 1023) g_bsum[b] = s[1023];
}
__global__ void scan2_kernel() {
    __shared__ int s[128];
    const int t = threadIdx.x;
    int v = (t < SCAN_BLOCKS) ? g_bsum[t] : 0;
    s[t] = v;
    __syncthreads();
    #pragma unroll
    for (int off = 1; off < 128; off <<= 1) {
        int x = (t >= off) ? s[t - off] : 0;
        __syncthreads();
        s[t] += x;
        __syncthreads();
    }
    if (t < SCAN_BLOCKS) g_bsum[t] = s[t] - v;   // exclusive
}
__global__ void scan3_kernel() {
    const int b = blockIdx.x, t = threadIdx.x;
    const int i = b * 1024 + t;
    if (i < N_NODES) g_rptr[i + 1] += g_bsum[b];
    if (i == 0) g_rptr[0] = 0;
}
__global__ void scatter_kernel(const int* __restrict__ erow,
                               const int* __restrict__ ecol,
                               const float* __restrict__ eval) {
    int e = blockIdx.x * blockDim.x + threadIdx.x;
    if (e < N_EDGES) {
        int r = erow[e];
        int pos = g_rptr[r] + atomicAdd(&g_cur[r], 1);
        g_edge[pos] = make_int2(ecol[e], __float_as_int(eval[e]));
    }
}

// ---------------- SpMM (+ReLU): fp16 gather, 2 feature chunks of 256 ------
// warp per row; edge {col,w} staged in SMEM, broadcast via LDS (no shuffles)
__global__ void __launch_bounds__(256) spmm_relu_chunk_kernel(int chunk)
{
    __shared__ int2 s_ed[8][32];
    const int wip  = threadIdx.x >> 5;            // warp in block
    const int lane = threadIdx.x & 31;
    const int gw   = blockIdx.x * 8 + wip;
    if (gw >= N_NODES) return;
    int beg = g_rptr[gw], end = g_rptr[gw + 1];
    const __half* hbase = g_h0h + (size_t)chunk * 256 + lane * 8;

    float acc[8];
    #pragma unroll
    for (int q = 0; q < 8; q++) acc[q] = 0.f;

    for (int b = beg; b < end; b += 32) {
        int n = end - b;
        if (n > 32) n = 32;
        if (lane < n) s_ed[wip][lane] = __ldcs(g_edge + b + lane);
        __syncwarp();
        for (int j = 0; j < n; j++) {
            int2 e = s_ed[wip][j];
            float wj = __int_as_float(e.y);
            uint4 v = *reinterpret_cast<const uint4*>(hbase + (size_t)e.x * 512);
            acc8(acc, wj, v);
        }
        __syncwarp();
    }
    __half* o = g_h1h + (size_t)gw * 512 + chunk * 256 + lane * 8;
    __stcs(reinterpret_cast<uint4*>(o), pack8(acc));
}

// ---------------- mma.sync fp16 GEMM ----------------
// C[M,N] = A[M,512] * W[N,512]^T.  A/B fp32 (inline cvt) or fp16.
// CTA tile 128x128, 16 warps (4m x 4n), warp tile 32x32.
// K chunks of 64, double-buffered SMEM.
#define MG_STAGE  32768
#define MG_A      0
#define MG_B      16384
#define MG_TOTAL  (2 * MG_STAGE)

template <bool A_HALF, bool B_HALF, bool RELU, bool HALF_OUT>
__global__ void __launch_bounds__(512) gemm_mma_kernel(
    const float* __restrict__ Af,
    const __half* __restrict__ Ah,
    const float* __restrict__ Bf,
    const __half* __restrict__ Bh,
    float* __restrict__ C,
    __half* __restrict__ Ch,
    int M, int N)
{
    extern __shared__ char smem[];
    const int tid  = threadIdx.x;
    const int wid  = tid >> 5;
    const int lane = tid & 31;
    const int bm = blockIdx.y * 128;
    const int bn = blockIdx.x * 128;
    const int wm = wid >> 2;       // 0..3
    const int wn = wid & 3;        // 0..3
    const uint32_t sb = smem_u32(smem);

    float d[2][4][4];
    #pragma unroll
    for (int mi = 0; mi < 2; mi++)
        #pragma unroll
        for (int ni = 0; ni < 4; ni++)
            #pragma unroll
            for (int q = 0; q < 4; q++) d[mi][ni][q] = 0.f;

    float4 paf[4], pbf[4];
    uint4  pah[2], pbh[2];

    const int lmat   = lane >> 3;
    const int a_rit  = ((lmat & 1) << 3) + (lane & 7);
    const int a_cadd = lmat >> 1;
    const int b_rit  = ((lmat >> 1) << 3) + (lane & 7);
    const int b_cadd = lmat & 1;

    int arow[2], brow[2];
    #pragma unroll
    for (int mi = 0; mi < 2; mi++) arow[mi] = wm * 32 + mi * 16 + a_rit;
    #pragma unroll
    for (int np = 0; np < 2; np++) brow[np] = wn * 32 + np * 16 + b_rit;

    #define LDG_CHUNK(kc) do {                                                     \
        const int k0_ = (kc) * 64;                                                 \
        if (A_HALF) {                                                              \
            _Pragma("unroll")                                                      \
            for (int i = 0; i < 2; i++) {                                          \
                int idx = tid + i * 512;                                           \
                int r = idx >> 3, c = idx & 7;                                     \
                int gr = bm + r;                                                   \
                pah[i] = (gr < M)                                                  \
                    ? __ldg(reinterpret_cast<const uint4*>(Ah + (size_t)gr * 512 + k0_) + c) \
                    : make_uint4(0u, 0u, 0u, 0u);                                  \
            }                                                                      \
        } else {                                                                   \
            _Pragma("unroll")                                                      \
            for (int i = 0; i < 4; i++) {                                          \
                int idx = tid + i * 512;                                           \
                int r = idx >> 4, c4 = idx & 15;                                   \
                int gr = bm + r;                                                   \
                paf[i] = (gr < M)                                                  \
                    ? __ldg(reinterpret_cast<const float4*>(Af + (size_t)gr * 512 + k0_ + c4 * 4)) \
                    : make_float4(0.f, 0.f, 0.f, 0.f);                             \
            }                                                                      \
        }                                                                          \
        if (B_HALF) {                                                              \
            _Pragma("unroll")                                                      \
            for (int i = 0; i < 2; i++) {                                          \
                int idx = tid + i * 512;                                           \
                int r = idx >> 3, c = idx & 7;                                     \
                size_t go = (size_t)(bn + r) * 512 + k0_;                          \
                pbh[i] = __ldg(reinterpret_cast<const uint4*>(Bh + go) + c);       \
            }                                                                      \
        } else {                                                                   \
            _Pragma("unroll")                                                      \
            for (int i = 0; i < 4; i++) {                                          \
                int idx = tid + i * 512;                                           \
                int r = idx >> 4, c4 = idx & 15;                                   \
                pbf[i] = __ldg(reinterpret_cast<const float4*>(Bf + (size_t)(bn + r) * 512 + k0_ + c4 * 4)); \
            }                                                                      \
        }                                                                          \
    } while (0)

    #define STS_CHUNK(s) do {                                                      \
        char* st_ = smem + (s) * MG_STAGE;                                         \
        if (A_HALF) {                                                              \
            _Pragma("unroll")                                                      \
            for (int i = 0; i < 2; i++) {                                          \
                int idx = tid + i * 512;                                           \
                int r = idx >> 3, c = idx & 7;                                     \
                uint32_t off = (uint32_t)(r * 128 + ((c ^ (r & 7)) << 4));         \
                *reinterpret_cast<uint4*>(st_ + MG_A + off) = pah[i];              \
            }                                                                      \
        } else {                                                                   \
            _Pragma("unroll")                                                      \
            for (int i = 0; i < 4; i++) {                                          \
                int idx = tid + i * 512;                                           \
                int r = idx >> 4, c4 = idx & 15;                                   \
                float4 v = paf[i];                                                 \
                __half2 h01 = __floats2half2_rn(v.x, v.y);                         \
                __half2 h23 = __floats2half2_rn(v.z, v.w);                         \
                int c = c4 >> 1, half = (c4 & 1) * 8;                              \
                uint32_t off = (uint32_t)(r * 128 + ((c ^ (r & 7)) << 4) + half);  \
                *reinterpret_cast<uint2*>(st_ + MG_A + off) =                      \
                    make_uint2(*reinterpret_cast<uint32_t*>(&h01),                 \
                               *reinterpret_cast<uint32_t*>(&h23));                \
            }                                                                      \
        }                                                                          \
        if (B_HALF) {                                                              \
            _Pragma("unroll")                                                      \
            for (int i = 0; i < 2; i++) {                                          \
                int idx = tid + i * 512;                                           \
                int r = idx >> 3, c = idx & 7;                                     \
                uint32_t off = (uint32_t)(r * 128 + ((c ^ (r & 7)) << 4));         \
                *reinterpret_cast<uint4*>(st_ + MG_B + off) = pbh[i];              \
            }                                                                      \
        } else {                                                                   \
            _Pragma("unroll")                                                      \
            for (int i = 0; i < 4; i++) {                                          \
                int idx = tid + i * 512;                                           \
                int r = idx >> 4, c4 = idx & 15;                                   \
                float4 v = pbf[i];                                                 \
                __half2 h01 = __floats2half2_rn(v.x, v.y);                         \
                __half2 h23 = __floats2half2_rn(v.z, v.w);                         \
                int c = c4 >> 1, half = (c4 & 1) * 8;                              \
                uint32_t off = (uint32_t)(r * 128 + ((c ^ (r & 7)) << 4) + half);  \
                *reinterpret_cast<uint2*>(st_ + MG_B + off) =                      \
                    make_uint2(*reinterpret_cast<uint32_t*>(&h01),                 \
                               *reinterpret_cast<uint32_t*>(&h23));                \
            }                                                                      \
        }                                                                          \
    } while (0)

    LDG_CHUNK(0);
    STS_CHUNK(0);
    __syncthreads();

    for (int kc = 0; kc < 8; kc++) {
        if (kc < 7) LDG_CHUNK(kc + 1);

        {
            const uint32_t ba = sb + (kc & 1) * MG_STAGE + MG_A;
            const uint32_t bb = sb + (kc & 1) * MG_STAGE + MG_B;
            #pragma unroll
            for (int ks = 0; ks < 4; ks++) {
                uint32_t af[2][4], bf[2][4];
                #pragma unroll
                for (int mi = 0; mi < 2; mi++) {
                    int cA = ks * 2 + a_cadd;
                    uint32_t off = (uint32_t)(arow[mi] * 128 + ((cA ^ (arow[mi] & 7)) << 4));
                    ldsm4(af[mi], ba + off);
                }
                #pragma unroll
                for (int np = 0; np < 2; np++) {
                    int cB = ks * 2 + b_cadd;
                    uint32_t off = (uint32_t)(brow[np] * 128 + ((cB ^ (brow[np] & 7)) << 4));
                    ldsm4(bf[np], bb + off);
                }
                #pragma unroll
                for (int mi = 0; mi < 2; mi++)
                    #pragma unroll
                    for (int np = 0; np < 2; np++)
                        #pragma unroll
                        for (int sub = 0; sub < 2; sub++)
                            mma16816h(d[mi][np * 2 + sub], af[mi],
                                      bf[np][sub * 2], bf[np][sub * 2 + 1]);
            }
        }

        if (kc < 7) STS_CHUNK((kc + 1) & 1);
        __syncthreads();
    }

    const int grp = lane >> 2;
    const int tg  = lane & 3;
    #pragma unroll
    for (int mi = 0; mi < 2; mi++) {
        #pragma unroll
        for (int ni = 0; ni < 4; ni++) {
            int row = bm + wm * 32 + mi * 16 + grp;
            int col = bn + wn * 32 + ni * 8 + tg * 2;
            float2 v0 = make_float2(d[mi][ni][0], d[mi][ni][1]);
            float2 v1 = make_float2(d[mi][ni][2], d[mi][ni][3]);
            if (RELU) {
                v0.x = fmaxf(v0.x, 0.f); v0.y = fmaxf(v0.y, 0.f);
                v1.x = fmaxf(v1.x, 0.f); v1.y = fmaxf(v1.y, 0.f);
            }
            if (HALF_OUT) {
                if (row < M)
                    *reinterpret_cast<__half2*>(Ch + (size_t)row * N + col) =
                        __floats2half2_rn(v0.x, v0.y);
                if (row + 8 < M)
                    *reinterpret_cast<__half2*>(Ch + (size_t)(row + 8) * N + col) =
                        __floats2half2_rn(v1.x, v1.y);
            } else {
                if (row < M)
                    *reinterpret_cast<float2*>(C + (size_t)row * N + col) = v0;
                if (row + 8 < M)
                    *reinterpret_cast<float2*>(C + (size_t)(row + 8) * N + col) = v1;
            }
        }
    }
    #undef LDG_CHUNK
    #undef STS_CHUNK
}

// ---------------- launch ----------------
extern "C" void kernel_launch(void* const* d_in, const int* in_sizes, int n_in,
                              void* d_out, int out_size)
{
    const float* x    = (const float*)d_in[0];
    const int*   erow = (const int*)  d_in[1];
    const int*   ecol = (const int*)  d_in[2];
    const float* eval = (const float*)d_in[3];
    const float* W0   = (const float*)d_in[4];
    const float* W1   = (const float*)d_in[5];
    const float* W2   = (const float*)d_in[6];
    float* out = (float*)d_out;

    __half *h0h, *h1h, *h2h, *wh;
    cudaGetSymbolAddress((void**)&h0h, g_h0h);
    cudaGetSymbolAddress((void**)&h1h, g_h1h);
    cudaGetSymbolAddress((void**)&h2h, g_h2h);
    cudaGetSymbolAddress((void**)&wh,  g_Wh);

    cudaFuncSetAttribute(gemm_mma_kernel<false, false, false, true>,
                         cudaFuncAttributeMaxDynamicSharedMemorySize, MG_TOTAL);
    cudaFuncSetAttribute(gemm_mma_kernel<true, true, true, true>,
                         cudaFuncAttributeMaxDynamicSharedMemorySize, MG_TOTAL);
    cudaFuncSetAttribute(gemm_mma_kernel<true, true, false, false>,
                         cudaFuncAttributeMaxDynamicSharedMemorySize, MG_TOTAL);

    static cudaStream_t s_side = nullptr;
    static cudaEvent_t  s_fork = nullptr, s_join = nullptr;
    if (s_side == nullptr) {
        cudaStreamCreateWithFlags(&s_side, cudaStreamNonBlocking);
        cudaEventCreateWithFlags(&s_fork, cudaEventDisableTiming);
        cudaEventCreateWithFlags(&s_join, cudaEventDisableTiming);
    }

    // fork: CSR build + W1/W2 conversion on side stream, under GEMM0
    cudaEventRecord(s_fork, 0);
    cudaStreamWaitEvent(s_side, s_fork, 0);
    convert_w_kernel<<<(W12_TOTAL + 255) / 256, 256, 0, s_side>>>(W1, W2);
    zero_counts_kernel<<<(N_NODES + 255) / 256, 256, 0, s_side>>>();
    hist_kernel<<<(N_EDGES + 255) / 256, 256, 0, s_side>>>(erow);
    scan1_kernel<<<SCAN_BLOCKS, 1024, 0, s_side>>>();
    scan2_kernel<<<1, 128, 0, s_side>>>();
    scan3_kernel<<<SCAN_BLOCKS, 1024, 0, s_side>>>();
    scatter_kernel<<<(N_EDGES + 255) / 256, 256, 0, s_side>>>(erow, ecol, eval);
    cudaEventRecord(s_join, s_side);

    // main stream: GEMM0 immediately (reads W0 fp32 directly, inline cvt)
    const int mtiles = (N_NODES + 127) / 128;
    gemm_mma_kernel<false, false, false, true><<<dim3(4, mtiles), 512, MG_TOTAL>>>(
        x, nullptr, W0, nullptr, nullptr, h0h, N_NODES, D_HID);

    // join: SpMM needs both GEMM0 (main) and CSR (side); GEMM1 needs W1 too
    cudaStreamWaitEvent(0, s_join, 0);
    for (int chunk = 0; chunk < 2; chunk++)
        spmm_relu_chunk_kernel<<<(N_NODES + 7) / 8, 256>>>(chunk);
    // h2 = relu(h1 @ W1^T)  (fp16 A, fp16 B, fp16 out)
    gemm_mma_kernel<true, true, true, true><<<dim3(4, mtiles), 512, MG_TOTAL>>>(
        nullptr, h1h, nullptr, wh + 262144, nullptr, h2h, N_NODES, D_HID);
    // out = h2 @ W2^T  (fp16 A, fp16 B, fp32 out)
    gemm_mma_kernel<true, true, false, false><<<dim3(2, mtiles), 512, MG_TOTAL>>>(
        nullptr, h2h, nullptr, wh + 524288, out, nullptr, N_NODES, D_OUT);
}